// round 5
// baseline (speedup 1.0000x reference)
#include <cuda_runtime.h>
#include <cuda_bf16.h>
#include <cstdint>

#define Bb 4
#define Tt 2048
#define Ee 512
#define KBLK 64
#define NBLK 32
#define MROWS (Bb * Tt)        // 8192
#define COMB_W (2 * Ee)        // 1024
#define NQKV (3 * Ee)          // 1536

// ---------------- scratch (__device__ globals) ------------------------------
__device__ __nv_bfloat16 g_xhi[MROWS * Ee];
__device__ __nv_bfloat16 g_xlo[MROWS * Ee];
__device__ __nv_bfloat16 g_Whi[NQKV * Ee];
__device__ __nv_bfloat16 g_Wlo[NQKV * Ee];
__device__ __nv_bfloat16 g_Uhi[Ee * COMB_W];
__device__ __nv_bfloat16 g_Ulo[Ee * COMB_W];
__device__ __nv_bfloat16 g_chi[MROWS * COMB_W];
__device__ __nv_bfloat16 g_clo[MROWS * COMB_W];
__device__ __nv_bfloat16 g_kqvh[MROWS * NQKV];       // K|Q|V bf16 hi
__device__ __nv_bfloat16 g_kqvl[MROWS * NQKV];       // K|Q|V bf16 lo
__device__ __nv_bfloat16 g_vth[Bb * Ee * Tt];        // V^T hi  [b][e][token]
__device__ __nv_bfloat16 g_vtl[Bb * Ee * Tt];        // V^T lo
__device__ float g_bias[NQKV];
__device__ float g_S1[Bb * NBLK * 64 * 64];          // 2 MB
__device__ float g_S2[Bb * NBLK * 64 * 32];          // 1 MB

// ---------------- PTX helpers ----------------------------------------------
__device__ __forceinline__ uint32_t smem_u32(const void* p) {
    uint32_t a;
    asm("{ .reg .u64 t; cvta.to.shared.u64 t, %1; cvt.u32.u64 %0, t; }"
        : "=r"(a) : "l"(p));
    return a;
}
#define CP_ASYNC16(dst, src) \
    asm volatile("cp.async.cg.shared.global [%0], [%1], 16;" :: "r"(dst), "l"(src))
#define CP_COMMIT() asm volatile("cp.async.commit_group;" ::: "memory")
#define CP_WAIT1()  asm volatile("cp.async.wait_group 1;" ::: "memory")
#define CP_WAIT0()  asm volatile("cp.async.wait_group 0;" ::: "memory")

__device__ __forceinline__ void ldm_x4(uint32_t* r, uint32_t addr) {
    asm volatile("ldmatrix.sync.aligned.m8n8.x4.shared.b16 {%0,%1,%2,%3}, [%4];"
                 : "=r"(r[0]), "=r"(r[1]), "=r"(r[2]), "=r"(r[3]) : "r"(addr));
}
__device__ __forceinline__ void mma16816(float* c, const uint32_t* a, const uint32_t* b) {
    asm volatile("mma.sync.aligned.m16n8k16.row.col.f32.bf16.bf16.f32 "
                 "{%0,%1,%2,%3}, {%4,%5,%6,%7}, {%8,%9}, {%0,%1,%2,%3};"
                 : "+f"(c[0]), "+f"(c[1]), "+f"(c[2]), "+f"(c[3])
                 : "r"(a[0]), "r"(a[1]), "r"(a[2]), "r"(a[3]), "r"(b[0]), "r"(b[1]));
}

__device__ __forceinline__ void split_pair_store(
    float x, float y, __nv_bfloat16* hi, __nv_bfloat16* lo, size_t off)
{
    __nv_bfloat16 h0 = __float2bfloat16(x);
    __nv_bfloat16 h1 = __float2bfloat16(y);
    __nv_bfloat16 l0 = __float2bfloat16(x - __bfloat162float(h0));
    __nv_bfloat16 l1 = __float2bfloat16(y - __bfloat162float(h1));
    __nv_bfloat162 hh; hh.x = h0; hh.y = h1;
    __nv_bfloat162 ll; ll.x = l0; ll.y = l1;
    *(__nv_bfloat162*)(hi + off) = hh;
    *(__nv_bfloat162*)(lo + off) = ll;
}

// ---------------- split-bf16 tensor-core NT GEMM ---------------------------
// mode: Chi==nullptr -> fp32 C (+bias). else -> split(acc+bias) to Chi/Clo.
#define ROWB 80
#define TILEB (128 * ROWB)
#define STAGEB (4 * TILEB)
#define GM_SMEM (2 * STAGEB)

__global__ __launch_bounds__(256) void gemm_mma(
    const __nv_bfloat16* __restrict__ Ahi, const __nv_bfloat16* __restrict__ Alo,
    const __nv_bfloat16* __restrict__ Bhi, const __nv_bfloat16* __restrict__ Blo,
    const float* __restrict__ bias, float* __restrict__ C,
    __nv_bfloat16* __restrict__ Chi, __nv_bfloat16* __restrict__ Clo,
    int Kd, int Nout)
{
    extern __shared__ char smem[];
    const uint32_t sbase = smem_u32(smem);
    const int tid = threadIdx.x;
    const int wid = tid >> 5, lane = tid & 31;
    const int warp_m = wid & 3, warp_n = wid >> 2;
    const int m0 = blockIdx.y * 128, n0 = blockIdx.x * 128;

    const int r0 = tid >> 2;
    const int r1 = r0 + 64;
    const int c0 = (tid & 3) * 16;
    const int ce = (tid & 3) * 8;

    auto load_stage = [&](int s, int k0) {
        uint32_t dst = sbase + (s & 1) * STAGEB;
        const __nv_bfloat16* srcs[4] = {
            Ahi + (size_t)(m0 + r0) * Kd + k0 + ce,
            Alo + (size_t)(m0 + r0) * Kd + k0 + ce,
            Bhi + (size_t)(n0 + r0) * Kd + k0 + ce,
            Blo + (size_t)(n0 + r0) * Kd + k0 + ce };
#pragma unroll
        for (int t = 0; t < 4; t++) {
            uint32_t d = dst + t * TILEB;
            CP_ASYNC16(d + r0 * ROWB + c0, srcs[t]);
            CP_ASYNC16(d + r1 * ROWB + c0, srcs[t] + (size_t)64 * Kd);
        }
        CP_COMMIT();
    };

    float acc[2][8][4] = {};
    const int nstages = Kd >> 5;
    load_stage(0, 0);

    for (int s = 0; s < nstages; s++) {
        if (s + 1 < nstages) { load_stage(s + 1, (s + 1) << 5); CP_WAIT1(); }
        else                 { CP_WAIT0(); }
        __syncthreads();

        const uint32_t st = sbase + (s & 1) * STAGEB;
        const uint32_t sAh = st, sAl = st + TILEB, sBh = st + 2 * TILEB, sBl = st + 3 * TILEB;

        const uint32_t aRow = (uint32_t)(warp_m * 32 + (lane & 15)) * ROWB + ((lane >> 4) & 1) * 16;
        const int g = lane >> 3, lr = lane & 7;
        const uint32_t bRowBase = (uint32_t)(warp_n * 64 + ((g >> 1) & 1) * 8 + lr) * ROWB + (g & 1) * 16;

#pragma unroll
        for (int ks = 0; ks < 2; ks++) {
            uint32_t ah[2][4], al[2][4];
#pragma unroll
            for (int mt = 0; mt < 2; mt++) {
                uint32_t ao = aRow + (uint32_t)mt * 16 * ROWB + ks * 32;
                ldm_x4(ah[mt], sAh + ao);
                ldm_x4(al[mt], sAl + ao);
            }
#pragma unroll
            for (int p = 0; p < 4; p++) {
                uint32_t bo = bRowBase + (uint32_t)p * 16 * ROWB + ks * 32;
                uint32_t bh[4], bl[4];
                ldm_x4(bh, sBh + bo);
                ldm_x4(bl, sBl + bo);
#pragma unroll
                for (int mt = 0; mt < 2; mt++)
#pragma unroll
                    for (int j = 0; j < 2; j++) {
                        float* cc = acc[mt][2 * p + j];
                        mma16816(cc, ah[mt], &bh[j * 2]);
                        mma16816(cc, ah[mt], &bl[j * 2]);
                        mma16816(cc, al[mt], &bh[j * 2]);
                    }
            }
        }
        __syncthreads();
    }

    const int mrow = m0 + warp_m * 32 + (lane >> 2);
    const int ncol0 = n0 + warp_n * 64 + (lane & 3) * 2;
#pragma unroll
    for (int mt = 0; mt < 2; mt++)
#pragma unroll
        for (int nt = 0; nt < 8; nt++) {
            int m = mrow + mt * 16;
            int n = ncol0 + nt * 8;
            float2 bv = *(const float2*)(bias + n);
            const float* cc = acc[mt][nt];
            float x0 = cc[0] + bv.x, y0 = cc[1] + bv.y;
            float x1 = cc[2] + bv.x, y1 = cc[3] + bv.y;
            if (Chi == nullptr) {
                float2 v0; v0.x = x0; v0.y = y0;
                float2 v1; v1.x = x1; v1.y = y1;
                *(float2*)(C + (size_t)m * Nout + n) = v0;
                *(float2*)(C + (size_t)(m + 8) * Nout + n) = v1;
            } else {
                split_pair_store(x0, y0, Chi, Clo, (size_t)m * Nout + n);
                split_pair_store(x1, y1, Chi, Clo, (size_t)(m + 8) * Nout + n);
            }
        }
}

// ---------------- conversion kernels ---------------------------------------
__global__ void split_kernel(const float* __restrict__ in,
                             __nv_bfloat16* __restrict__ hi,
                             __nv_bfloat16* __restrict__ lo, int n)
{
    for (int i = blockIdx.x * blockDim.x + threadIdx.x; i < n; i += gridDim.x * blockDim.x) {
        float v = in[i];
        __nv_bfloat16 h = __float2bfloat16(v);
        hi[i] = h;
        lo[i] = __float2bfloat16(v - __bfloat162float(h));
    }
}

// all weights + biases in one launch
#define W3N  (3 * Ee * Ee)              // 786432
#define WUN  (Ee * COMB_W)              // 524288
#define WTOT (W3N + WUN + NQKV)
__global__ void wsplit_all(const float* __restrict__ Wk, const float* __restrict__ Wq,
                           const float* __restrict__ Wv, const float* __restrict__ Wu,
                           const float* __restrict__ bk, const float* __restrict__ bq,
                           const float* __restrict__ bv)
{
    for (int i = blockIdx.x * blockDim.x + threadIdx.x; i < WTOT; i += gridDim.x * blockDim.x) {
        if (i < W3N) {
            int wsel = i >> 18;                 // / 262144
            int off = i & 262143;
            const float* W = (wsel == 0) ? Wk : (wsel == 1) ? Wq : Wv;
            float v = W[off];
            __nv_bfloat16 h = __float2bfloat16(v);
            g_Whi[i] = h;
            g_Wlo[i] = __float2bfloat16(v - __bfloat162float(h));
        } else if (i < W3N + WUN) {
            int off = i - W3N;
            float v = Wu[off];
            __nv_bfloat16 h = __float2bfloat16(v);
            g_Uhi[off] = h;
            g_Ulo[off] = __float2bfloat16(v - __bfloat162float(h));
        } else {
            int off = i - W3N - WUN;            // 0..1535
            g_bias[off] = (off < Ee) ? bk[off] : (off < 2 * Ee) ? bq[off - Ee] : bv[off - 2 * Ee];
        }
    }
}

// ---------------- V transpose: g_kqvh/l[:, 1024:1536] -> g_vth/l[b][e][t] ---
__global__ __launch_bounds__(256) void vt_kernel()
{
    __shared__ __nv_bfloat16 th[32][33];
    __shared__ __nv_bfloat16 tl[32][33];
    const int t0 = blockIdx.x * 32, e0 = blockIdx.y * 32, b = blockIdx.z;
    const int tx = threadIdx.x & 31, ty = threadIdx.x >> 5;   // 32 x 8
#pragma unroll
    for (int l = 0; l < 4; l++) {
        int t = t0 + ty + l * 8;
        size_t src = ((size_t)b * Tt + t) * NQKV + 2 * Ee + e0 + tx;
        th[ty + l * 8][tx] = g_kqvh[src];
        tl[ty + l * 8][tx] = g_kqvl[src];
    }
    __syncthreads();
#pragma unroll
    for (int l = 0; l < 4; l++) {
        int e = e0 + ty + l * 8;
        size_t dst = ((size_t)b * Ee + e) * Tt + t0 + tx;
        g_vth[dst] = th[tx][ty + l * 8];
        g_vtl[dst] = tl[tx][ty + l * 8];
    }
}

// ---------------- head1 score: S[64x64] = K_blk . Q_blk^T (K=512) ----------
// grid (NBLK, Bb), 128 threads (4 warps: 2m x 2n, warp tile 32x32)
__global__ __launch_bounds__(128) void h1_score()
{
    const int blk = blockIdx.x, b = blockIdx.y;
    const int tid = threadIdx.x, wid = tid >> 5, lane = tid & 31;
    const int warp_m = wid >> 1, warp_n = wid & 1;
    const size_t rbase = (size_t)b * Tt + (size_t)blk * KBLK;
    __shared__ char smem[2 * 20480];
    const uint32_t sb = smem_u32(smem);

    auto load_stage = [&](int s, int k0) {
        uint32_t dst = sb + (s & 1) * 20480;
#pragma unroll
        for (int j = 0; j < 8; j++) {
            int flat = tid * 8 + j;             // 0..1023
            int c = flat & 3, r = (flat >> 2) & 63, t = flat >> 8;
            const __nv_bfloat16* base = (t & 1) ? g_kqvl : g_kqvh;
            int coloff = ((t >= 2) ? Ee : 0) + k0 + c * 8;
            CP_ASYNC16(dst + t * 5120 + r * 80 + c * 16,
                       base + (rbase + r) * NQKV + coloff);
        }
        CP_COMMIT();
    };

    float acc[2][4][4] = {};
    load_stage(0, 0);
    for (int s = 0; s < 16; s++) {
        if (s < 15) { load_stage(s + 1, (s + 1) * 32); CP_WAIT1(); }
        else        { CP_WAIT0(); }
        __syncthreads();
        const uint32_t st = sb + (s & 1) * 20480;
        const uint32_t sKh = st, sKl = st + 5120, sQh = st + 10240, sQl = st + 15360;
        const uint32_t aRow = (uint32_t)(warp_m * 32 + (lane & 15)) * 80 + ((lane >> 4) & 1) * 16;
        const int g = lane >> 3, lr = lane & 7;
        const uint32_t bRow = (uint32_t)(warp_n * 32 + ((g >> 1) & 1) * 8 + lr) * 80 + (g & 1) * 16;
#pragma unroll
        for (int ks = 0; ks < 2; ks++) {
            uint32_t ah[2][4], al[2][4];
#pragma unroll
            for (int mt = 0; mt < 2; mt++) {
                uint32_t ao = aRow + (uint32_t)mt * 16 * 80 + ks * 32;
                ldm_x4(ah[mt], sKh + ao);
                ldm_x4(al[mt], sKl + ao);
            }
#pragma unroll
            for (int p = 0; p < 2; p++) {
                uint32_t bo = bRow + (uint32_t)p * 16 * 80 + ks * 32;
                uint32_t bh[4], bl[4];
                ldm_x4(bh, sQh + bo);
                ldm_x4(bl, sQl + bo);
#pragma unroll
                for (int mt = 0; mt < 2; mt++)
#pragma unroll
                    for (int j = 0; j < 2; j++) {
                        float* cc = acc[mt][2 * p + j];
                        mma16816(cc, ah[mt], &bh[j * 2]);
                        mma16816(cc, ah[mt], &bl[j * 2]);
                        mma16816(cc, al[mt], &bh[j * 2]);
                    }
            }
        }
        __syncthreads();
    }
    float* dst = g_S1 + ((size_t)b * NBLK + blk) * 4096;
    const int rr = warp_m * 32 + (lane >> 2);
    const int cc0 = warp_n * 32 + (lane & 3) * 2;
#pragma unroll
    for (int mt = 0; mt < 2; mt++)
#pragma unroll
        for (int nt = 0; nt < 4; nt++) {
            int r = rr + mt * 16, c = cc0 + nt * 8;
            float2 v0; v0.x = acc[mt][nt][0]; v0.y = acc[mt][nt][1];
            float2 v1; v1.x = acc[mt][nt][2]; v1.y = acc[mt][nt][3];
            *(float2*)(dst + r * 64 + c) = v0;
            *(float2*)(dst + (r + 8) * 64 + c) = v1;
        }
}

// ---------------- head2 score: S2[64x32] = K_rt . Q_starts^T (K=512) -------
// grid (NBLK, Bb), 128 threads (4 warps: 4m, warp tile 16x32)
__global__ __launch_bounds__(128) void h2_score()
{
    const int rt = blockIdx.x, b = blockIdx.y;
    const int tid = threadIdx.x, wid = tid >> 5, lane = tid & 31;
    const size_t rbase = (size_t)b * Tt + (size_t)rt * KBLK;
    __shared__ char smem[2 * 15360];
    const uint32_t sb = smem_u32(smem);

    auto load_stage = [&](int s, int k0) {
        uint32_t dst = sb + (s & 1) * 15360;
#pragma unroll
        for (int j = 0; j < 6; j++) {
            int flat = tid + 128 * j;
            if (flat < 512) {                    // K tiles
                int c = flat & 3, r = (flat >> 2) & 63, t = flat >> 8;
                const __nv_bfloat16* base = t ? g_kqvl : g_kqvh;
                CP_ASYNC16(dst + t * 5120 + r * 80 + c * 16,
                           base + (rbase + r) * NQKV + k0 + c * 8);
            } else {                              // Q gather tiles
                int fb = flat - 512;
                int c = fb & 3, r = (fb >> 2) & 31, t = fb >> 7;
                const __nv_bfloat16* base = t ? g_kqvl : g_kqvh;
                CP_ASYNC16(dst + 10240 + t * 2560 + r * 80 + c * 16,
                           base + ((size_t)b * Tt + (size_t)r * KBLK) * NQKV + Ee + k0 + c * 8);
            }
        }
        CP_COMMIT();
    };

    float acc[4][4] = {};
    load_stage(0, 0);
    for (int s = 0; s < 16; s++) {
        if (s < 15) { load_stage(s + 1, (s + 1) * 32); CP_WAIT1(); }
        else        { CP_WAIT0(); }
        __syncthreads();
        const uint32_t st = sb + (s & 1) * 15360;
        const uint32_t sKh = st, sKl = st + 5120, sQh = st + 10240, sQl = st + 12800;
        const uint32_t aRow = (uint32_t)(wid * 16 + (lane & 15)) * 80 + ((lane >> 4) & 1) * 16;
        const int g = lane >> 3, lr = lane & 7;
        const uint32_t bRow = (uint32_t)(((g >> 1) & 1) * 8 + lr) * 80 + (g & 1) * 16;
#pragma unroll
        for (int ks = 0; ks < 2; ks++) {
            uint32_t ah[4], al[4];
            uint32_t ao = aRow + ks * 32;
            ldm_x4(ah, sKh + ao);
            ldm_x4(al, sKl + ao);
#pragma unroll
            for (int p = 0; p < 2; p++) {
                uint32_t bo = bRow + (uint32_t)p * 16 * 80 + ks * 32;
                uint32_t bh[4], bl[4];
                ldm_x4(bh, sQh + bo);
                ldm_x4(bl, sQl + bo);
#pragma unroll
                for (int j = 0; j < 2; j++) {
                    float* cc = acc[2 * p + j];
                    mma16816(cc, ah, &bh[j * 2]);
                    mma16816(cc, ah, &bl[j * 2]);
                    mma16816(cc, al, &bh[j * 2]);
                }
            }
        }
        __syncthreads();
    }
    float* dst = g_S2 + ((size_t)b * NBLK + rt) * 2048;
    const int rr = wid * 16 + (lane >> 2);
    const int cc0 = (lane & 3) * 2;
#pragma unroll
    for (int nt = 0; nt < 4; nt++) {
        int c = cc0 + nt * 8;
        float2 v0; v0.x = acc[nt][0]; v0.y = acc[nt][1];
        float2 v1; v1.x = acc[nt][2]; v1.y = acc[nt][3];
        *(float2*)(dst + rr * 32 + c) = v0;
        *(float2*)(dst + (rr + 8) * 32 + c) = v1;
    }
}

// ---------------- head1 out: comb[:,0:512] = mask(S) @ V_blk ---------------
// grid (NBLK, Bb, 2), 256 threads (8 warps: 4m x 2n)
#define SROW 144
#define VROW 144
#define H1O_SMEM (2 * 64 * SROW + 2 * 128 * VROW)   // 18432 + 36864 = 55296
__global__ __launch_bounds__(256) void h1_out()
{
    extern __shared__ char smem[];
    const int blk = blockIdx.x, b = blockIdx.y, ec = blockIdx.z;
    const int tid = threadIdx.x, wid = tid >> 5, lane = tid & 31;
    const int warp_m = wid & 3, warp_n = wid >> 2;
    const size_t rbase = (size_t)b * Tt + (size_t)blk * KBLK;
    const uint32_t sb = smem_u32(smem);
    const uint32_t sSh = sb, sSl = sb + 64 * SROW;
    const uint32_t sVh = sb + 2 * 64 * SROW, sVl = sVh + 128 * VROW;

    // load + mask + split S
    {
        const float* sp = g_S1 + ((size_t)b * NBLK + blk) * 4096;
        int r = tid >> 2, cbeg = (tid & 3) * 16;
#pragma unroll
        for (int c = cbeg; c < cbeg + 16; c++) {
            float v = (c <= r) ? sp[r * 64 + c] : 0.0f;
            __nv_bfloat16 h = __float2bfloat16(v);
            __nv_bfloat16 l = __float2bfloat16(v - __bfloat162float(h));
            *(__nv_bfloat16*)(smem + r * SROW + c * 2) = h;
            *(__nv_bfloat16*)(smem + 64 * SROW + r * SROW + c * 2) = l;
        }
    }
    __syncthreads();

    // A fragments (S) — fixed across n-iterations
    uint32_t ah[4][4], al[4][4];
    {
        const uint32_t aRow = (uint32_t)(warp_m * 16 + (lane & 15)) * SROW + ((lane >> 4) & 1) * 16;
#pragma unroll
        for (int ks = 0; ks < 4; ks++) {
            ldm_x4(ah[ks], sSh + aRow + ks * 32);
            ldm_x4(al[ks], sSl + aRow + ks * 32);
        }
    }

    for (int it = 0; it < 2; it++) {
        __syncthreads();
        // Vt tile: rows e = ec*256 + it*128 + r (128), cols = tokens of this blk (64)
#pragma unroll
        for (int j = 0; j < 8; j++) {
            int flat = tid * 8 + j;              // 0..2047
            int c = flat & 7, r = (flat >> 3) & 127, t = flat >> 10;
            const __nv_bfloat16* src = (t ? g_vtl : g_vth) +
                ((size_t)b * Ee + ec * 256 + it * 128 + r) * Tt + (size_t)blk * KBLK + c * 8;
            char* d = smem + 2 * 64 * SROW + t * 128 * VROW + r * VROW + c * 16;
            *(float4*)d = *(const float4*)src;
        }
        __syncthreads();

        float acc[8][4] = {};
        const int g = lane >> 3, lr = lane & 7;
        const uint32_t bRow = (uint32_t)(warp_n * 64 + ((g >> 1) & 1) * 8 + lr) * VROW + (g & 1) * 16;
#pragma unroll
        for (int ks = 0; ks < 4; ks++)
#pragma unroll
            for (int p = 0; p < 4; p++) {
                uint32_t bo = bRow + (uint32_t)p * 16 * VROW + ks * 32;
                uint32_t bh[4], bl[4];
                ldm_x4(bh, sVh + bo);
                ldm_x4(bl, sVl + bo);
#pragma unroll
                for (int j = 0; j < 2; j++) {
                    float* cc = acc[2 * p + j];
                    mma16816(cc, ah[ks], &bh[j * 2]);
                    mma16816(cc, ah[ks], &bl[j * 2]);
                    mma16816(cc, al[ks], &bh[j * 2]);
                }
            }

        const int rr = warp_m * 16 + (lane >> 2);
        const int col0 = ec * 256 + it * 128 + warp_n * 64 + (lane & 3) * 2;
#pragma unroll
        for (int nt = 0; nt < 8; nt++) {
            int col = col0 + nt * 8;
            size_t row = rbase + rr;
            split_pair_store(acc[nt][0], acc[nt][1], g_chi, g_clo, row * COMB_W + col);
            split_pair_store(acc[nt][2], acc[nt][3], g_chi, g_clo, (row + 8) * COMB_W + col);
        }
    }
}

// ---------------- head2 out: comb[:,512:1024] = mask(S2) @ V_starts --------
// grid (NBLK, Bb, 2), 256 threads (8 warps: 4m x 2n), k = 32
#define SROW2 80
#define VROW2 80
__global__ __launch_bounds__(256) void h2_out()
{
    __shared__ char smem[2 * 64 * SROW2 + 2 * 128 * VROW2];   // 10240 + 20480
    const int rt = blockIdx.x, b = blockIdx.y, ec = blockIdx.z;
    const int tid = threadIdx.x, wid = tid >> 5, lane = tid & 31;
    const int warp_m = wid & 3, warp_n = wid >> 2;
    const size_t rbase = (size_t)b * Tt + (size_t)rt * KBLK;
    const uint32_t sb = smem_u32(smem);
    const uint32_t sSh = sb, sSl = sb + 64 * SROW2;
    const uint32_t sVh = sb + 2 * 64 * SROW2, sVl = sVh + 128 * VROW2;

    {
        const float* sp = g_S2 + ((size_t)b * NBLK + rt) * 2048;
        int r = tid >> 2, cbeg = (tid & 3) * 8;
#pragma unroll
        for (int c = cbeg; c < cbeg + 8; c++) {
            float v = (c <= rt) ? sp[r * 32 + c] : 0.0f;
            __nv_bfloat16 h = __float2bfloat16(v);
            __nv_bfloat16 l = __float2bfloat16(v - __bfloat162float(h));
            *(__nv_bfloat16*)(smem + r * SROW2 + c * 2) = h;
            *(__nv_bfloat16*)(smem + 64 * SROW2 + r * SROW2 + c * 2) = l;
        }
    }
    __syncthreads();

    uint32_t ah[2][4], al[2][4];
    {
        const uint32_t aRow = (uint32_t)(warp_m * 16 + (lane & 15)) * SROW2 + ((lane >> 4) & 1) * 16;
#pragma unroll
        for (int ks = 0; ks < 2; ks++) {
            ldm_x4(ah[ks], sSh + aRow + ks * 32);
            ldm_x4(al[ks], sSl + aRow + ks * 32);
        }
    }

    for (int it = 0; it < 2; it++) {
        __syncthreads();
        // Vt gather tile: rows e (128), cols i (32) at tokens i*64
        {
            int r = tid >> 1, half = tid & 1;     // 128 rows, 2 halves of 16 cols
            size_t ebase = ((size_t)b * Ee + ec * 256 + it * 128 + r) * Tt;
            for (int i = half * 16; i < half * 16 + 16; i++) {
                __nv_bfloat16 vh = g_vth[ebase + (size_t)i * KBLK];
                __nv_bfloat16 vl = g_vtl[ebase + (size_t)i * KBLK];
                *(__nv_bfloat16*)(smem + 2 * 64 * SROW2 + r * VROW2 + i * 2) = vh;
                *(__nv_bfloat16*)(smem + 2 * 64 * SROW2 + 128 * VROW2 + r * VROW2 + i * 2) = vl;
            }
        }
        __syncthreads();

        float acc[8][4] = {};
        const int g = lane >> 3, lr = lane & 7;
        const uint32_t bRow = (uint32_t)(warp_n * 64 + ((g >> 1) & 1) * 8 + lr) * VROW2 + (g & 1) * 16;
#pragma unroll
        for (int ks = 0; ks < 2; ks++)
#pragma unroll
            for (int p = 0; p < 4; p++) {
                uint32_t bo = bRow + (uint32_t)p * 16 * VROW2 + ks * 32;
                uint32_t bh[4], bl[4];
                ldm_x4(bh, sVh + bo);
                ldm_x4(bl, sVl + bo);
#pragma unroll
                for (int j = 0; j < 2; j++) {
                    float* cc = acc[2 * p + j];
                    mma16816(cc, ah[ks], &bh[j * 2]);
                    mma16816(cc, ah[ks], &bl[j * 2]);
                    mma16816(cc, al[ks], &bh[j * 2]);
                }
            }

        const int rr = warp_m * 16 + (lane >> 2);
        const int col0 = Ee + ec * 256 + it * 128 + warp_n * 64 + (lane & 3) * 2;
#pragma unroll
        for (int nt = 0; nt < 8; nt++) {
            int col = col0 + nt * 8;
            size_t row = rbase + rr;
            split_pair_store(acc[nt][0], acc[nt][1], g_chi, g_clo, row * COMB_W + col);
            split_pair_store(acc[nt][2], acc[nt][3], g_chi, g_clo, (row + 8) * COMB_W + col);
        }
    }
}

// ---------------------------------------------------------------------------
extern "C" void kernel_launch(void* const* d_in, const int* in_sizes, int n_in,
                              void* d_out, int out_size)
{
    const float* x  = (const float*)d_in[0];
    const float* Wk = (const float*)d_in[1];
    const float* bk = (const float*)d_in[2];
    const float* Wq = (const float*)d_in[3];
    const float* bq = (const float*)d_in[4];
    const float* Wv = (const float*)d_in[5];
    const float* bv = (const float*)d_in[6];
    const float* Wu = (const float*)d_in[7];
    const float* bu = (const float*)d_in[8];
    float* out = (float*)d_out;

    float *pBias;
    __nv_bfloat16 *pxh, *pxl, *pWh, *pWl, *pUh, *pUl, *pch, *pcl, *pkh, *pkl;
    cudaGetSymbolAddress((void**)&pBias, g_bias);
    cudaGetSymbolAddress((void**)&pxh, g_xhi);
    cudaGetSymbolAddress((void**)&pxl, g_xlo);
    cudaGetSymbolAddress((void**)&pWh, g_Whi);
    cudaGetSymbolAddress((void**)&pWl, g_Wlo);
    cudaGetSymbolAddress((void**)&pUh, g_Uhi);
    cudaGetSymbolAddress((void**)&pUl, g_Ulo);
    cudaGetSymbolAddress((void**)&pch, g_chi);
    cudaGetSymbolAddress((void**)&pcl, g_clo);
    cudaGetSymbolAddress((void**)&pkh, g_kqvh);
    cudaGetSymbolAddress((void**)&pkl, g_kqvl);

    cudaFuncSetAttribute(gemm_mma, cudaFuncAttributeMaxDynamicSharedMemorySize, GM_SMEM);
    cudaFuncSetAttribute(h1_out, cudaFuncAttributeMaxDynamicSharedMemorySize, H1O_SMEM);

    // 1) input split, 2) fused weight/bias split
    split_kernel<<<1024, 256>>>(x, pxh, pxl, MROWS * Ee);
    wsplit_all<<<640, 256>>>(Wk, Wq, Wv, Wu, bk, bq, bv);

    // 3) fused QKV projection -> bf16 hi/lo (bias added pre-split)
    gemm_mma<<<dim3(NQKV / 128, MROWS / 128), 256, GM_SMEM>>>(
        pxh, pxl, pWh, pWl, pBias, nullptr, pkh, pkl, Ee, NQKV);

    // 4) V transpose
    vt_kernel<<<dim3(Tt / 32, Ee / 32, Bb), 256>>>();

    // 5-8) heads (tensorized)
    h1_score<<<dim3(NBLK, Bb), 128>>>();
    h2_score<<<dim3(NBLK, Bb), 128>>>();
    h1_out<<<dim3(NBLK, Bb, 2), 256, H1O_SMEM>>>();
    h2_out<<<dim3(NBLK, Bb, 2), 256>>>();

    // 9) final projection (fp32 out + bias)
    gemm_mma<<<dim3(Ee / 128, MROWS / 128), 256, GM_SMEM>>>(
        pch, pcl, pUh, pUl, bu, out, nullptr, nullptr, COMB_W, Ee);
}